// round 2
// baseline (speedup 1.0000x reference)
#include <cuda_runtime.h>
#include <cstdint>

// Problem constants
#define BATCH  4
#define SEQ    2048
#define DMODEL 1024

// Scratch (device globals: allocation-free)
__device__ float g_Q[(size_t)BATCH * SEQ * DMODEL];
__device__ float g_K[(size_t)BATCH * SEQ * DMODEL];
__device__ float g_V[(size_t)BATCH * SEQ * DMODEL];
__device__ float g_S[(size_t)BATCH * SEQ * SEQ];

// ---------------------------------------------------------------------------
// Tiled fp32 SGEMM: C[z] = alpha * A[z] @ B[z](^T) (+ bias)
// BM=BN=128, BK=8, 256 threads, 8x8 per thread. All dims divide evenly here.
// ---------------------------------------------------------------------------
template <bool TRANSB, bool HASBIAS>
__global__ __launch_bounds__(256, 2)
void sgemm_k(const float* __restrict__ Ag, const float* __restrict__ Bg,
             const float* __restrict__ bias, float* __restrict__ Cg,
             int M, int N, int K, float alpha,
             long long sA, long long sB, long long sC)
{
    const int z = blockIdx.z;
    const float* __restrict__ A  = Ag + (long long)z * sA;
    const float* __restrict__ Bp = Bg + (long long)z * sB;
    float* __restrict__ C        = Cg + (long long)z * sC;

    __shared__ float As[8][128];
    __shared__ float Bs[8][128];

    const int tid  = threadIdx.x;
    const int row0 = blockIdx.y * 128;
    const int col0 = blockIdx.x * 128;
    const int tx   = tid & 15;   // n-direction (8 cols each)
    const int ty   = tid >> 4;   // m-direction (8 rows each)

    // tile-load lane assignment
    const int lRow = tid >> 1;          // 0..127
    const int lCol = (tid & 1) << 2;    // 0 or 4
    const int bRow = tid >> 5;          // 0..7   (non-trans B)
    const int bCol = (tid & 31) << 2;   // 0..124

    float acc[8][8];
#pragma unroll
    for (int i = 0; i < 8; i++)
#pragma unroll
        for (int j = 0; j < 8; j++) acc[i][j] = 0.0f;

    const float* Aptr = A + (long long)(row0 + lRow) * K + lCol;
    const float* Bptr = TRANSB ? (Bp + (long long)(col0 + lRow) * K + lCol)
                               : (Bp + (long long)bRow * N + col0 + bCol);

    for (int k0 = 0; k0 < K; k0 += 8) {
        float4 av = *(const float4*)(Aptr + k0);
        float4 bv;
        if (TRANSB) bv = *(const float4*)(Bptr + k0);
        else        bv = *(const float4*)(Bptr + (long long)k0 * N);

        As[lCol + 0][lRow] = av.x;
        As[lCol + 1][lRow] = av.y;
        As[lCol + 2][lRow] = av.z;
        As[lCol + 3][lRow] = av.w;
        if (TRANSB) {
            Bs[lCol + 0][lRow] = bv.x;
            Bs[lCol + 1][lRow] = bv.y;
            Bs[lCol + 2][lRow] = bv.z;
            Bs[lCol + 3][lRow] = bv.w;
        } else {
            *(float4*)&Bs[bRow][bCol] = bv;
        }
        __syncthreads();

#pragma unroll
        for (int kk = 0; kk < 8; kk++) {
            float ra[8], rb[8];
            *(float4*)&ra[0] = *(const float4*)&As[kk][ty * 8];
            *(float4*)&ra[4] = *(const float4*)&As[kk][ty * 8 + 4];
            *(float4*)&rb[0] = *(const float4*)&Bs[kk][tx * 8];
            *(float4*)&rb[4] = *(const float4*)&Bs[kk][tx * 8 + 4];
#pragma unroll
            for (int i = 0; i < 8; i++)
#pragma unroll
                for (int j = 0; j < 8; j++)
                    acc[i][j] += ra[i] * rb[j];
        }
        __syncthreads();
    }

#pragma unroll
    for (int i = 0; i < 8; i++) {
        const long long row = row0 + ty * 8 + i;
#pragma unroll
        for (int j = 0; j < 8; j += 4) {
            const int col = col0 + tx * 8 + j;
            float4 v;
            v.x = acc[i][j + 0] * alpha;
            v.y = acc[i][j + 1] * alpha;
            v.z = acc[i][j + 2] * alpha;
            v.w = acc[i][j + 3] * alpha;
            if (HASBIAS) {
                v.x += bias[col + 0];
                v.y += bias[col + 1];
                v.z += bias[col + 2];
                v.w += bias[col + 3];
            }
            *(float4*)(C + row * N + col) = v;
        }
    }
}

// ---------------------------------------------------------------------------
// JAX threefry2x32 with key (0, 42)  == jax.random.key(42)
// Partitionable scheme (modern JAX default): for flat element index i,
//   (y0, y1) = threefry2x32(key, x0=hi32(i)=0, x1=lo32(i)=i)
//   bits[i]  = y0 ^ y1 ;  keep <=> MSB(bits)==0  (uniform<0.5)
// ---------------------------------------------------------------------------
__device__ __forceinline__ uint32_t threefry_mask_word(uint32_t idx)
{
    const uint32_t ks0 = 0u;
    const uint32_t ks1 = 42u;
    const uint32_t ks2 = 42u ^ 0x1BD11BDAu;
    uint32_t x0 = ks0;           // hi counter = 0
    uint32_t x1 = idx + ks1;     // lo counter = idx
#define TFR(r) { x0 += x1; x1 = __funnelshift_l(x1, x1, (r)); x1 ^= x0; }
    TFR(13) TFR(15) TFR(26) TFR(6)
    x0 += ks1; x1 += ks2 + 1u;
    TFR(17) TFR(29) TFR(16) TFR(24)
    x0 += ks2; x1 += ks0 + 2u;
    TFR(13) TFR(15) TFR(26) TFR(6)
    x0 += ks0; x1 += ks1 + 3u;
    TFR(17) TFR(29) TFR(16) TFR(24)
    x0 += ks1; x1 += ks2 + 4u;
    TFR(13) TFR(15) TFR(26) TFR(6)
    x0 += ks2; x1 += ks0 + 5u;
#undef TFR
    return x0 ^ x1;
}

// ---------------------------------------------------------------------------
// Softmax + dropout, one block per (b,q) row of S.
// kept value = p * 2  (1/(1-0.5) folded into the row normalizer).
// ---------------------------------------------------------------------------
__global__ __launch_bounds__(256, 4)
void softmax_dropout_k(float* __restrict__ S)
{
    const int q   = blockIdx.x;
    const int b   = blockIdx.y;
    const int tid = threadIdx.x;
    float* __restrict__ row = S + ((size_t)b * SEQ + q) * SEQ;

    float a[8];
#pragma unroll
    for (int j = 0; j < 8; j++) a[j] = row[tid + j * 256];

    // --- max reduce ---
    float m = a[0];
#pragma unroll
    for (int j = 1; j < 8; j++) m = fmaxf(m, a[j]);
#pragma unroll
    for (int s = 16; s > 0; s >>= 1)
        m = fmaxf(m, __shfl_xor_sync(0xffffffffu, m, s));
    __shared__ float red[8];
    const int wid = tid >> 5, lane = tid & 31;
    if (lane == 0) red[wid] = m;
    __syncthreads();
    m = red[0];
#pragma unroll
    for (int w = 1; w < 8; w++) m = fmaxf(m, red[w]);
    __syncthreads();

    // --- exp + sum reduce ---
    float s0 = 0.0f;
#pragma unroll
    for (int j = 0; j < 8; j++) {
        a[j] = __expf(a[j] - m);
        s0 += a[j];
    }
#pragma unroll
    for (int s = 16; s > 0; s >>= 1)
        s0 += __shfl_xor_sync(0xffffffffu, s0, s);
    if (lane == 0) red[wid] = s0;
    __syncthreads();
    s0 = 0.0f;
#pragma unroll
    for (int w = 0; w < 8; w++) s0 += red[w];

    const float inv = 2.0f / s0;   // dropout 1/(1-p)=2 folded in

    const uint32_t base = ((uint32_t)(b * SEQ + q)) * (uint32_t)SEQ;
#pragma unroll
    for (int j = 0; j < 8; j++) {
        const uint32_t k = (uint32_t)tid + (uint32_t)j * 256u;
        const uint32_t w = threefry_mask_word(base + k);
        row[k] = (w >> 31) ? 0.0f : a[j] * inv;
    }
}

// ---------------------------------------------------------------------------
// Launcher
// ---------------------------------------------------------------------------
extern "C" void kernel_launch(void* const* d_in, const int* in_sizes, int n_in,
                              void* d_out, int out_size)
{
    (void)in_sizes; (void)n_in; (void)out_size;
    const float* query = (const float*)d_in[0];
    const float* key_  = (const float*)d_in[1];
    const float* value = (const float*)d_in[2];
    const float* Wq    = (const float*)d_in[3];
    const float* bq    = (const float*)d_in[4];
    const float* Wk    = (const float*)d_in[5];
    const float* bk    = (const float*)d_in[6];
    const float* Wv    = (const float*)d_in[7];
    const float* bv    = (const float*)d_in[8];
    float* out = (float*)d_out;

    float *dQ, *dK, *dV, *dS;
    cudaGetSymbolAddress((void**)&dQ, g_Q);
    cudaGetSymbolAddress((void**)&dK, g_K);
    cudaGetSymbolAddress((void**)&dV, g_V);
    cudaGetSymbolAddress((void**)&dS, g_S);

    const int M  = BATCH * SEQ;            // 8192
    const long long sQK = (long long)SEQ * DMODEL;   // per-batch Q/K/V stride
    const long long sS  = (long long)SEQ * SEQ;      // per-batch score stride

    dim3 thr(256);

    // 1) Projections: X @ W + b  -> g_{Q,K,V}
    dim3 gProj(DMODEL / 128, M / 128, 1);
    sgemm_k<false, true><<<gProj, thr>>>(query, Wq, bq, dQ, M, DMODEL, DMODEL, 1.0f, 0, 0, 0);
    sgemm_k<false, true><<<gProj, thr>>>(key_,  Wk, bk, dK, M, DMODEL, DMODEL, 1.0f, 0, 0, 0);
    sgemm_k<false, true><<<gProj, thr>>>(value, Wv, bv, dV, M, DMODEL, DMODEL, 1.0f, 0, 0, 0);

    // 2) Scores: S = 8 * Q @ K^T  (per batch)
    dim3 gScore(SEQ / 128, SEQ / 128, BATCH);
    sgemm_k<true, false><<<gScore, thr>>>(dQ, dK, nullptr, dS, SEQ, SEQ, DMODEL, 8.0f, sQK, sQK, sS);

    // 3) Softmax + threefry dropout (in place on S)
    dim3 gSm(SEQ, BATCH, 1);
    softmax_dropout_k<<<gSm, thr>>>(dS);

    // 4) Output: O = P @ V  (per batch)
    dim3 gOut(DMODEL / 128, SEQ / 128, BATCH);
    sgemm_k<false, false><<<gOut, thr>>>(dS, dV, nullptr, out, SEQ, DMODEL, SEQ, 1.0f, sS, sQK, sQK);
}

// round 4
// speedup vs baseline: 1.5518x; 1.5518x over previous
#include <cuda_runtime.h>
#include <cstdint>

// ---------------------------------------------------------------------------
// Problem constants
// ---------------------------------------------------------------------------
#define BATCH  4
#define SEQ    2048
#define DMODEL 1024

// Scratch (device globals: allocation-free)
__device__ float g_Q[(size_t)BATCH * SEQ * DMODEL];
__device__ float g_K[(size_t)BATCH * SEQ * DMODEL];
__device__ float g_V[(size_t)BATCH * SEQ * DMODEL];
__device__ float g_S[(size_t)BATCH * SEQ * SEQ];

// ---------------------------------------------------------------------------
// Helpers
// ---------------------------------------------------------------------------
__device__ __forceinline__ uint32_t smem_u32(const void* p) {
    uint32_t a;
    asm("{ .reg .u64 t; cvta.to.shared.u64 t, %1; cvt.u32.u64 %0, t; }"
        : "=r"(a) : "l"(p));
    return a;
}

#define CP_ASYNC16(saddr, gptr) \
    asm volatile("cp.async.cg.shared.global [%0], [%1], 16;" \
        :: "r"(saddr), "l"(gptr) : "memory")
#define CP_COMMIT() asm volatile("cp.async.commit_group;" ::: "memory")
#define CP_WAIT0()  asm volatile("cp.async.wait_group 0;" ::: "memory")
#define CP_WAIT1()  asm volatile("cp.async.wait_group 1;" ::: "memory")

// tf32x3 split: hi = top 10 mantissa bits (valid tf32), lo = rounded residual
__device__ __forceinline__ void split3(float x, uint32_t& hi, uint32_t& lo) {
    const uint32_t h = __float_as_uint(x) & 0xffffe000u;
    hi = h;
    const float l = x - __uint_as_float(h);
    uint32_t lt;
    asm("cvt.rna.tf32.f32 %0, %1;" : "=r"(lt) : "f"(l));
    lo = lt;
}

// D += A(16x8 tf32) * B(8x8 tf32), fp32 accumulate
__device__ __forceinline__ void mma8(float* d, const uint32_t* a, const uint32_t* b) {
    asm volatile(
        "mma.sync.aligned.m16n8k8.row.col.f32.tf32.tf32.f32 "
        "{%0,%1,%2,%3}, {%4,%5,%6,%7}, {%8,%9}, {%0,%1,%2,%3};"
        : "+f"(d[0]), "+f"(d[1]), "+f"(d[2]), "+f"(d[3])
        : "r"(a[0]), "r"(a[1]), "r"(a[2]), "r"(a[3]), "r"(b[0]), "r"(b[1]));
}

// ---------------------------------------------------------------------------
// tf32x3 GEMM body: C[m,n] = alpha * sum_k A[m,k]*Bmat[k,n] (+ bias[n])
//   TRANSB_LOAD=false: Bmat[k,n] = B[n*ldb + k]  (B K-major [N,K], e.g. K^T)
//   TRANSB_LOAD=true : Bmat[k,n] = B[k*ldb + n]  (B MN-major [K,N], e.g. W, V)
// BM=BN=128, KC=32, 256 threads (8 warps, each 64x32), cp.async 2-stage.
// ---------------------------------------------------------------------------
#define A_TILE_F 4608            // 128 * 36 floats
#define B_TILE_F 4608            // >= max(128*36 direct, 32*136 trans)
#define STAGE_F  (A_TILE_F + B_TILE_F)
#define GEMM_SMEM_BYTES (2 * STAGE_F * 4)

template <bool TRANSB_LOAD, bool HASBIAS>
__device__ __forceinline__
void gemm_body(const float* __restrict__ A, const float* __restrict__ B,
               const float* __restrict__ bias, float* __restrict__ C,
               int K, int lda, int ldb, int ldc, float alpha)
{
    extern __shared__ float smem[];

    const int tid  = threadIdx.x;
    const int wid  = tid >> 5;
    const int lane = tid & 31;
    const int tg   = lane >> 2;      // 0..7
    const int tk   = lane & 3;       // 0..3
    const int row0 = blockIdx.y * 128;
    const int col0 = blockIdx.x * 128;
    const int wm   = (wid >> 2) * 64;   // warp m-offset in tile
    const int wn   = (wid & 3) * 32;    // warp n-offset in tile

    float acc[4][4][4];
#pragma unroll
    for (int mt = 0; mt < 4; mt++)
#pragma unroll
        for (int nt = 0; nt < 4; nt++)
#pragma unroll
            for (int e = 0; e < 4; e++) acc[mt][nt][e] = 0.0f;

    // ---- stage fill via cp.async ----
    auto fill = [&](int st, int k0) {
        float* base = smem + st * STAGE_F;
        const uint32_t sAa = smem_u32(base);
        const uint32_t sBa = smem_u32(base + A_TILE_F);
        // A tile: [128 m][32 k], k-contiguous global
#pragma unroll
        for (int j = 0; j < 4; j++) {
            const int idx = tid + j * 256;
            const int r  = idx >> 3;
            const int c4 = (idx & 7) << 2;
            CP_ASYNC16(sAa + (uint32_t)(r * 36 + c4) * 4u,
                       A + (size_t)(row0 + r) * lda + k0 + c4);
        }
        if (TRANSB_LOAD) {
            // B global [K,N] n-contiguous -> smem [32 k][128 n], ld=136
#pragma unroll
            for (int j = 0; j < 4; j++) {
                const int idx = tid + j * 256;
                const int kk = idx >> 5;
                const int n4 = (idx & 31) << 2;
                CP_ASYNC16(sBa + (uint32_t)(kk * 136 + n4) * 4u,
                           B + (size_t)(k0 + kk) * ldb + col0 + n4);
            }
        } else {
            // B global [N,K] k-contiguous -> smem [128 n][32 k], ld=36
#pragma unroll
            for (int j = 0; j < 4; j++) {
                const int idx = tid + j * 256;
                const int r  = idx >> 3;
                const int c4 = (idx & 7) << 2;
                CP_ASYNC16(sBa + (uint32_t)(r * 36 + c4) * 4u,
                           B + (size_t)(col0 + r) * ldb + k0 + c4);
            }
        }
        CP_COMMIT();
    };

    // ---- compute one staged chunk (4 k8-steps) ----
    auto compute = [&](int st) {
        const float* sA = smem + st * STAGE_F;
        const float* sB = sA + A_TILE_F;
#pragma unroll
        for (int s = 0; s < 4; s++) {
            uint32_t ah[4][4], al[4][4], bh[4][2], bl[4][2];
#pragma unroll
            for (int mt = 0; mt < 4; mt++) {
                const int m0 = wm + mt * 16;
                const float a0 = sA[(m0 + tg)     * 36 + s * 8 + tk];
                const float a1 = sA[(m0 + tg + 8) * 36 + s * 8 + tk];
                const float a2 = sA[(m0 + tg)     * 36 + s * 8 + tk + 4];
                const float a3 = sA[(m0 + tg + 8) * 36 + s * 8 + tk + 4];
                split3(a0, ah[mt][0], al[mt][0]);
                split3(a1, ah[mt][1], al[mt][1]);
                split3(a2, ah[mt][2], al[mt][2]);
                split3(a3, ah[mt][3], al[mt][3]);
            }
#pragma unroll
            for (int nt = 0; nt < 4; nt++) {
                const int n0 = wn + nt * 8;
                float b0, b1;
                if (TRANSB_LOAD) {
                    b0 = sB[(s * 8 + tk)     * 136 + n0 + tg];
                    b1 = sB[(s * 8 + tk + 4) * 136 + n0 + tg];
                } else {
                    b0 = sB[(n0 + tg) * 36 + s * 8 + tk];
                    b1 = sB[(n0 + tg) * 36 + s * 8 + tk + 4];
                }
                split3(b0, bh[nt][0], bl[nt][0]);
                split3(b1, bh[nt][1], bl[nt][1]);
            }
#pragma unroll
            for (int mt = 0; mt < 4; mt++)
#pragma unroll
                for (int nt = 0; nt < 4; nt++) {
                    mma8(acc[mt][nt], ah[mt], bh[nt]);
                    mma8(acc[mt][nt], ah[mt], bl[nt]);
                    mma8(acc[mt][nt], al[mt], bh[nt]);
                }
        }
    };

    const int nchunk = K >> 5;   // K/32
    fill(0, 0);
    for (int i = 0; i < nchunk; i++) {
        if (i + 1 < nchunk) {
            fill((i + 1) & 1, (i + 1) << 5);
            CP_WAIT1();
        } else {
            CP_WAIT0();
        }
        __syncthreads();
        compute(i & 1);
        __syncthreads();
    }

    // ---- epilogue ----
#pragma unroll
    for (int mt = 0; mt < 4; mt++) {
        const int r = row0 + wm + mt * 16 + tg;
#pragma unroll
        for (int nt = 0; nt < 4; nt++) {
            const int col = col0 + wn + nt * 8 + tk * 2;
            float2 v0, v1;
            v0.x = acc[mt][nt][0] * alpha;
            v0.y = acc[mt][nt][1] * alpha;
            v1.x = acc[mt][nt][2] * alpha;
            v1.y = acc[mt][nt][3] * alpha;
            if (HASBIAS) {
                const float b0 = bias[col], b1 = bias[col + 1];
                v0.x += b0; v0.y += b1;
                v1.x += b0; v1.y += b1;
            }
            *(float2*)(C + (size_t)r * ldc + col)       = v0;
            *(float2*)(C + (size_t)(r + 8) * ldc + col) = v1;
        }
    }
}

// Generic batched GEMM kernel
template <bool TRANSB_LOAD, bool HASBIAS>
__global__ __launch_bounds__(256)
void mma_gemm_k(const float* __restrict__ Ag, const float* __restrict__ Bg,
                const float* __restrict__ bias, float* __restrict__ Cg,
                int K, int lda, int ldb, int ldc, float alpha,
                long long sA, long long sB, long long sC)
{
    const int z = blockIdx.z;
    gemm_body<TRANSB_LOAD, HASBIAS>(Ag + (long long)z * sA,
                                    Bg + (long long)z * sB,
                                    bias, Cg + (long long)z * sC,
                                    K, lda, ldb, ldc, alpha);
}

// Fused Q/K/V projection: blockIdx.z picks which projection
__global__ __launch_bounds__(256)
void mma_proj3_k(const float* __restrict__ q, const float* __restrict__ k,
                 const float* __restrict__ v,
                 const float* __restrict__ Wq, const float* __restrict__ bq,
                 const float* __restrict__ Wk, const float* __restrict__ bk,
                 const float* __restrict__ Wv, const float* __restrict__ bv,
                 float* __restrict__ Q, float* __restrict__ K, float* __restrict__ V)
{
    const float *A, *B, *bias;
    float* C;
    if (blockIdx.z == 0)      { A = q; B = Wq; bias = bq; C = Q; }
    else if (blockIdx.z == 1) { A = k; B = Wk; bias = bk; C = K; }
    else                      { A = v; B = Wv; bias = bv; C = V; }
    gemm_body<true, true>(A, B, bias, C, DMODEL, DMODEL, DMODEL, DMODEL, 1.0f);
}

// ---------------------------------------------------------------------------
// JAX threefry2x32, key (0,42), partitionable scheme:
//   bits[i] = y0 ^ y1 of threefry2x32(key, (0, i)); keep <=> MSB==0
// ---------------------------------------------------------------------------
__device__ __forceinline__ uint32_t threefry_mask_word(uint32_t idx)
{
    const uint32_t ks0 = 0u;
    const uint32_t ks1 = 42u;
    const uint32_t ks2 = 42u ^ 0x1BD11BDAu;
    uint32_t x0 = ks0;
    uint32_t x1 = idx + ks1;
#define TFR(r) { x0 += x1; x1 = __funnelshift_l(x1, x1, (r)); x1 ^= x0; }
    TFR(13) TFR(15) TFR(26) TFR(6)
    x0 += ks1; x1 += ks2 + 1u;
    TFR(17) TFR(29) TFR(16) TFR(24)
    x0 += ks2; x1 += ks0 + 2u;
    TFR(13) TFR(15) TFR(26) TFR(6)
    x0 += ks0; x1 += ks1 + 3u;
    TFR(17) TFR(29) TFR(16) TFR(24)
    x0 += ks1; x1 += ks2 + 4u;
    TFR(13) TFR(15) TFR(26) TFR(6)
    x0 += ks2; x1 += ks0 + 5u;
#undef TFR
    return x0 ^ x1;
}

// ---------------------------------------------------------------------------
// Softmax + dropout, one block per (b,q) row of S. kept value scaled by 2.
// ---------------------------------------------------------------------------
__global__ __launch_bounds__(256, 4)
void softmax_dropout_k(float* __restrict__ S)
{
    const int q   = blockIdx.x;
    const int b   = blockIdx.y;
    const int tid = threadIdx.x;
    float* __restrict__ row = S + ((size_t)b * SEQ + q) * SEQ;

    float a[8];
#pragma unroll
    for (int j = 0; j < 8; j++) a[j] = row[tid + j * 256];

    float m = a[0];
#pragma unroll
    for (int j = 1; j < 8; j++) m = fmaxf(m, a[j]);
#pragma unroll
    for (int s = 16; s > 0; s >>= 1)
        m = fmaxf(m, __shfl_xor_sync(0xffffffffu, m, s));
    __shared__ float red[8];
    const int wid = tid >> 5, lane = tid & 31;
    if (lane == 0) red[wid] = m;
    __syncthreads();
    m = red[0];
#pragma unroll
    for (int w = 1; w < 8; w++) m = fmaxf(m, red[w]);
    __syncthreads();

    float s0 = 0.0f;
#pragma unroll
    for (int j = 0; j < 8; j++) {
        a[j] = __expf(a[j] - m);
        s0 += a[j];
    }
#pragma unroll
    for (int s = 16; s > 0; s >>= 1)
        s0 += __shfl_xor_sync(0xffffffffu, s0, s);
    if (lane == 0) red[wid] = s0;
    __syncthreads();
    s0 = 0.0f;
#pragma unroll
    for (int w = 0; w < 8; w++) s0 += red[w];

    const float inv = 2.0f / s0;

    const uint32_t base = ((uint32_t)(b * SEQ + q)) * (uint32_t)SEQ;
#pragma unroll
    for (int j = 0; j < 8; j++) {
        const uint32_t k = (uint32_t)tid + (uint32_t)j * 256u;
        const uint32_t w = threefry_mask_word(base + k);
        row[k] = (w >> 31) ? 0.0f : a[j] * inv;
    }
}

// ---------------------------------------------------------------------------
// Launcher
// ---------------------------------------------------------------------------
extern "C" void kernel_launch(void* const* d_in, const int* in_sizes, int n_in,
                              void* d_out, int out_size)
{
    (void)in_sizes; (void)n_in; (void)out_size;
    const float* query = (const float*)d_in[0];
    const float* key_  = (const float*)d_in[1];
    const float* value = (const float*)d_in[2];
    const float* Wq    = (const float*)d_in[3];
    const float* bq    = (const float*)d_in[4];
    const float* Wk    = (const float*)d_in[5];
    const float* bk    = (const float*)d_in[6];
    const float* Wv    = (const float*)d_in[7];
    const float* bv    = (const float*)d_in[8];
    float* out = (float*)d_out;

    float *dQ, *dK, *dV, *dS;
    cudaGetSymbolAddress((void**)&dQ, g_Q);
    cudaGetSymbolAddress((void**)&dK, g_K);
    cudaGetSymbolAddress((void**)&dV, g_V);
    cudaGetSymbolAddress((void**)&dS, g_S);

    static bool attr_done = false;
    if (!attr_done) {
        cudaFuncSetAttribute(mma_proj3_k,
                             cudaFuncAttributeMaxDynamicSharedMemorySize, GEMM_SMEM_BYTES);
        cudaFuncSetAttribute(mma_gemm_k<false, false>,
                             cudaFuncAttributeMaxDynamicSharedMemorySize, GEMM_SMEM_BYTES);
        cudaFuncSetAttribute(mma_gemm_k<true, false>,
                             cudaFuncAttributeMaxDynamicSharedMemorySize, GEMM_SMEM_BYTES);
        attr_done = true;
    }

    const long long sQK = (long long)SEQ * DMODEL;
    const long long sS  = (long long)SEQ * SEQ;
    dim3 thr(256);

    // 1) Projections (fused, grid.z picks q/k/v)
    dim3 gProj(DMODEL / 128, (BATCH * SEQ) / 128, 3);
    mma_proj3_k<<<gProj, thr, GEMM_SMEM_BYTES>>>(
        query, key_, value, Wq, bq, Wk, bk, Wv, bv, dQ, dK, dV);

    // 2) Scores: S = 8 * Q @ K^T (K matrix is K-major [N,K] -> direct)
    dim3 gScore(SEQ / 128, SEQ / 128, BATCH);
    mma_gemm_k<false, false><<<gScore, thr, GEMM_SMEM_BYTES>>>(
        dQ, dK, nullptr, dS, DMODEL, DMODEL, DMODEL, SEQ, 8.0f, sQK, sQK, sS);

    // 3) Softmax + threefry dropout (in place on S)
    dim3 gSm(SEQ, BATCH, 1);
    softmax_dropout_k<<<gSm, thr>>>(dS);

    // 4) Output: O = P @ V  (V is MN-major [K=2048, N=1024] -> transpose-load)
    dim3 gOut(DMODEL / 128, SEQ / 128, BATCH);
    mma_gemm_k<true, false><<<gOut, thr, GEMM_SMEM_BYTES>>>(
        dS, dV, nullptr, out, SEQ, SEQ, DMODEL, DMODEL, 1.0f, sS, sQK, sQK);
}

// round 5
// speedup vs baseline: 1.6806x; 1.0830x over previous
#include <cuda_runtime.h>
#include <cstdint>

// ---------------------------------------------------------------------------
// Problem constants
// ---------------------------------------------------------------------------
#define BATCH  4
#define SEQ    2048
#define DMODEL 1024

// Scratch (device globals: allocation-free)
__device__ float g_Q[(size_t)BATCH * SEQ * DMODEL];
__device__ float g_K[(size_t)BATCH * SEQ * DMODEL];
__device__ float g_V[(size_t)BATCH * SEQ * DMODEL];
__device__ float g_S[(size_t)BATCH * SEQ * SEQ];

// ---------------------------------------------------------------------------
// Helpers
// ---------------------------------------------------------------------------
__device__ __forceinline__ uint32_t smem_u32(const void* p) {
    uint32_t a;
    asm("{ .reg .u64 t; cvta.to.shared.u64 t, %1; cvt.u32.u64 %0, t; }"
        : "=r"(a) : "l"(p));
    return a;
}

#define CP_ASYNC16(saddr, gptr) \
    asm volatile("cp.async.cg.shared.global [%0], [%1], 16;" \
        :: "r"(saddr), "l"(gptr) : "memory")
#define CP_COMMIT() asm volatile("cp.async.commit_group;" ::: "memory")
#define CP_WAIT0()  asm volatile("cp.async.wait_group 0;" ::: "memory")
#define CP_WAIT1()  asm volatile("cp.async.wait_group 1;" ::: "memory")

// tf32x3 split: hi = top 10 mantissa bits (valid tf32), lo = rounded residual
__device__ __forceinline__ void split3(float x, uint32_t& hi, uint32_t& lo) {
    const uint32_t h = __float_as_uint(x) & 0xffffe000u;
    hi = h;
    const float l = x - __uint_as_float(h);
    uint32_t lt;
    asm("cvt.rna.tf32.f32 %0, %1;" : "=r"(lt) : "f"(l));
    lo = lt;
}

// D += A(16x8 tf32) * B(8x8 tf32), fp32 accumulate
__device__ __forceinline__ void mma8(float* d, const uint32_t* a, const uint32_t* b) {
    asm volatile(
        "mma.sync.aligned.m16n8k8.row.col.f32.tf32.tf32.f32 "
        "{%0,%1,%2,%3}, {%4,%5,%6,%7}, {%8,%9}, {%0,%1,%2,%3};"
        : "+f"(d[0]), "+f"(d[1]), "+f"(d[2]), "+f"(d[3])
        : "r"(a[0]), "r"(a[1]), "r"(a[2]), "r"(a[3]), "r"(b[0]), "r"(b[1]));
}

// ---------------------------------------------------------------------------
// tf32x3 GEMM body: C[m,n] = alpha * sum_k A[m,k]*Bmat[k,n] (+ bias[n])
//   TRANSB_LOAD=false: Bmat[k,n] = B[n*ldb + k]  (B K-major [N,K], e.g. K^T)
//   TRANSB_LOAD=true : Bmat[k,n] = B[k*ldb + n]  (B MN-major [K,N], e.g. W, V)
// BM=BN=128, KC=32, 256 threads (8 warps, each 64x32), cp.async 2-stage.
// Register-lean loop order to allow 2 CTAs/SM.
// ---------------------------------------------------------------------------
#define A_TILE_F 4608            // 128 * 36 floats
#define B_TILE_F 4608            // >= max(128*36 direct, 32*136 trans)
#define STAGE_F  (A_TILE_F + B_TILE_F)
#define GEMM_SMEM_BYTES (2 * STAGE_F * 4)

template <bool TRANSB_LOAD, bool HASBIAS>
__device__ __forceinline__
void gemm_body(const float* __restrict__ A, const float* __restrict__ B,
               const float* __restrict__ bias, float* __restrict__ C,
               int K, int lda, int ldb, int ldc, float alpha)
{
    extern __shared__ float smem[];

    const int tid  = threadIdx.x;
    const int wid  = tid >> 5;
    const int lane = tid & 31;
    const int tg   = lane >> 2;      // 0..7
    const int tk   = lane & 3;       // 0..3
    const int row0 = blockIdx.y * 128;
    const int col0 = blockIdx.x * 128;
    const int wm   = (wid >> 2) * 64;   // warp m-offset in tile
    const int wn   = (wid & 3) * 32;    // warp n-offset in tile

    float acc[4][4][4];
#pragma unroll
    for (int mt = 0; mt < 4; mt++)
#pragma unroll
        for (int nt = 0; nt < 4; nt++)
#pragma unroll
            for (int e = 0; e < 4; e++) acc[mt][nt][e] = 0.0f;

    // ---- stage fill via cp.async ----
    auto fill = [&](int st, int k0) {
        float* base = smem + st * STAGE_F;
        const uint32_t sAa = smem_u32(base);
        const uint32_t sBa = smem_u32(base + A_TILE_F);
        // A tile: [128 m][32 k], k-contiguous global
#pragma unroll
        for (int j = 0; j < 4; j++) {
            const int idx = tid + j * 256;
            const int r  = idx >> 3;
            const int c4 = (idx & 7) << 2;
            CP_ASYNC16(sAa + (uint32_t)(r * 36 + c4) * 4u,
                       A + (size_t)(row0 + r) * lda + k0 + c4);
        }
        if (TRANSB_LOAD) {
            // B global [K,N] n-contiguous -> smem [32 k][128 n], ld=136
#pragma unroll
            for (int j = 0; j < 4; j++) {
                const int idx = tid + j * 256;
                const int kk = idx >> 5;
                const int n4 = (idx & 31) << 2;
                CP_ASYNC16(sBa + (uint32_t)(kk * 136 + n4) * 4u,
                           B + (size_t)(k0 + kk) * ldb + col0 + n4);
            }
        } else {
            // B global [N,K] k-contiguous -> smem [128 n][32 k], ld=36
#pragma unroll
            for (int j = 0; j < 4; j++) {
                const int idx = tid + j * 256;
                const int r  = idx >> 3;
                const int c4 = (idx & 7) << 2;
                CP_ASYNC16(sBa + (uint32_t)(r * 36 + c4) * 4u,
                           B + (size_t)(col0 + r) * ldb + k0 + c4);
            }
        }
        CP_COMMIT();
    };

    // ---- compute one staged chunk (4 k8-steps), register-lean order ----
    auto compute = [&](int st) {
        const float* sA = smem + st * STAGE_F;
        const float* sB = sA + A_TILE_F;
#pragma unroll
        for (int s = 0; s < 4; s++) {
            // B fragments for all 4 nt (16 regs live)
            uint32_t bh[4][2], bl[4][2];
#pragma unroll
            for (int nt = 0; nt < 4; nt++) {
                const int n0 = wn + nt * 8;
                float b0, b1;
                if (TRANSB_LOAD) {
                    b0 = sB[(s * 8 + tk)     * 136 + n0 + tg];
                    b1 = sB[(s * 8 + tk + 4) * 136 + n0 + tg];
                } else {
                    b0 = sB[(n0 + tg) * 36 + s * 8 + tk];
                    b1 = sB[(n0 + tg) * 36 + s * 8 + tk + 4];
                }
                split3(b0, bh[nt][0], bl[nt][0]);
                split3(b1, bh[nt][1], bl[nt][1]);
            }
            // A fragments per mt (8 regs live at a time)
#pragma unroll
            for (int mt = 0; mt < 4; mt++) {
                const int m0 = wm + mt * 16;
                uint32_t ah[4], al[4];
                const float a0 = sA[(m0 + tg)     * 36 + s * 8 + tk];
                const float a1 = sA[(m0 + tg + 8) * 36 + s * 8 + tk];
                const float a2 = sA[(m0 + tg)     * 36 + s * 8 + tk + 4];
                const float a3 = sA[(m0 + tg + 8) * 36 + s * 8 + tk + 4];
                split3(a0, ah[0], al[0]);
                split3(a1, ah[1], al[1]);
                split3(a2, ah[2], al[2]);
                split3(a3, ah[3], al[3]);
#pragma unroll
                for (int nt = 0; nt < 4; nt++) {
                    mma8(acc[mt][nt], ah, bh[nt]);
                    mma8(acc[mt][nt], ah, bl[nt]);
                    mma8(acc[mt][nt], al, bh[nt]);
                }
            }
        }
    };

    const int nchunk = K >> 5;   // K/32
    fill(0, 0);
    for (int i = 0; i < nchunk; i++) {
        if (i + 1 < nchunk) {
            fill((i + 1) & 1, (i + 1) << 5);
            CP_WAIT1();
        } else {
            CP_WAIT0();
        }
        __syncthreads();
        compute(i & 1);
        __syncthreads();
    }

    // ---- epilogue ----
#pragma unroll
    for (int mt = 0; mt < 4; mt++) {
        const int r = row0 + wm + mt * 16 + tg;
#pragma unroll
        for (int nt = 0; nt < 4; nt++) {
            const int col = col0 + wn + nt * 8 + tk * 2;
            float2 v0, v1;
            v0.x = acc[mt][nt][0] * alpha;
            v0.y = acc[mt][nt][1] * alpha;
            v1.x = acc[mt][nt][2] * alpha;
            v1.y = acc[mt][nt][3] * alpha;
            if (HASBIAS) {
                const float b0 = bias[col], b1 = bias[col + 1];
                v0.x += b0; v0.y += b1;
                v1.x += b0; v1.y += b1;
            }
            *(float2*)(C + (size_t)r * ldc + col)       = v0;
            *(float2*)(C + (size_t)(r + 8) * ldc + col) = v1;
        }
    }
}

// Generic batched GEMM kernel (2 CTAs/SM)
template <bool TRANSB_LOAD, bool HASBIAS>
__global__ __launch_bounds__(256, 2)
void mma_gemm_k(const float* __restrict__ Ag, const float* __restrict__ Bg,
                const float* __restrict__ bias, float* __restrict__ Cg,
                int K, int lda, int ldb, int ldc, float alpha,
                long long sA, long long sB, long long sC)
{
    const int z = blockIdx.z;
    gemm_body<TRANSB_LOAD, HASBIAS>(Ag + (long long)z * sA,
                                    Bg + (long long)z * sB,
                                    bias, Cg + (long long)z * sC,
                                    K, lda, ldb, ldc, alpha);
}

// Fused Q/K/V projection: blockIdx.z picks which projection
__global__ __launch_bounds__(256, 2)
void mma_proj3_k(const float* __restrict__ q, const float* __restrict__ k,
                 const float* __restrict__ v,
                 const float* __restrict__ Wq, const float* __restrict__ bq,
                 const float* __restrict__ Wk, const float* __restrict__ bk,
                 const float* __restrict__ Wv, const float* __restrict__ bv,
                 float* __restrict__ Q, float* __restrict__ K, float* __restrict__ V)
{
    const float *A, *B, *bias;
    float* C;
    if (blockIdx.z == 0)      { A = q; B = Wq; bias = bq; C = Q; }
    else if (blockIdx.z == 1) { A = k; B = Wk; bias = bk; C = K; }
    else                      { A = v; B = Wv; bias = bv; C = V; }
    gemm_body<true, true>(A, B, bias, C, DMODEL, DMODEL, DMODEL, DMODEL, 1.0f);
}

// ---------------------------------------------------------------------------
// JAX threefry2x32, key (0,42), partitionable scheme:
//   bits[i] = y0 ^ y1 of threefry2x32(key, (0, i)); keep <=> MSB==0
// ---------------------------------------------------------------------------
__device__ __forceinline__ uint32_t threefry_mask_word(uint32_t idx)
{
    const uint32_t ks0 = 0u;
    const uint32_t ks1 = 42u;
    const uint32_t ks2 = 42u ^ 0x1BD11BDAu;
    uint32_t x0 = ks0;
    uint32_t x1 = idx + ks1;
#define TFR(r) { x0 += x1; x1 = __funnelshift_l(x1, x1, (r)); x1 ^= x0; }
    TFR(13) TFR(15) TFR(26) TFR(6)
    x0 += ks1; x1 += ks2 + 1u;
    TFR(17) TFR(29) TFR(16) TFR(24)
    x0 += ks2; x1 += ks0 + 2u;
    TFR(13) TFR(15) TFR(26) TFR(6)
    x0 += ks0; x1 += ks1 + 3u;
    TFR(17) TFR(29) TFR(16) TFR(24)
    x0 += ks1; x1 += ks2 + 4u;
    TFR(13) TFR(15) TFR(26) TFR(6)
    x0 += ks2; x1 += ks0 + 5u;
#undef TFR
    return x0 ^ x1;
}

// ---------------------------------------------------------------------------
// Softmax + dropout, one block per (b,q) row of S. kept value scaled by 2.
// ---------------------------------------------------------------------------
__global__ __launch_bounds__(256, 4)
void softmax_dropout_k(float* __restrict__ S)
{
    const int q   = blockIdx.x;
    const int b   = blockIdx.y;
    const int tid = threadIdx.x;
    float* __restrict__ row = S + ((size_t)b * SEQ + q) * SEQ;

    float a[8];
#pragma unroll
    for (int j = 0; j < 8; j++) a[j] = row[tid + j * 256];

    float m = a[0];
#pragma unroll
    for (int j = 1; j < 8; j++) m = fmaxf(m, a[j]);
#pragma unroll
    for (int s = 16; s > 0; s >>= 1)
        m = fmaxf(m, __shfl_xor_sync(0xffffffffu, m, s));
    __shared__ float red[8];
    const int wid = tid >> 5, lane = tid & 31;
    if (lane == 0) red[wid] = m;
    __syncthreads();
    m = red[0];
#pragma unroll
    for (int w = 1; w < 8; w++) m = fmaxf(m, red[w]);
    __syncthreads();

    float s0 = 0.0f;
#pragma unroll
    for (int j = 0; j < 8; j++) {
        a[j] = __expf(a[j] - m);
        s0 += a[j];
    }
#pragma unroll
    for (int s = 16; s > 0; s >>= 1)
        s0 += __shfl_xor_sync(0xffffffffu, s0, s);
    if (lane == 0) red[wid] = s0;
    __syncthreads();
    s0 = 0.0f;
#pragma unroll
    for (int w = 0; w < 8; w++) s0 += red[w];

    const float inv = 2.0f / s0;

    const uint32_t base = ((uint32_t)(b * SEQ + q)) * (uint32_t)SEQ;
#pragma unroll
    for (int j = 0; j < 8; j++) {
        const uint32_t k = (uint32_t)tid + (uint32_t)j * 256u;
        const uint32_t w = threefry_mask_word(base + k);
        row[k] = (w >> 31) ? 0.0f : a[j] * inv;
    }
}

// ---------------------------------------------------------------------------
// Launcher
// ---------------------------------------------------------------------------
extern "C" void kernel_launch(void* const* d_in, const int* in_sizes, int n_in,
                              void* d_out, int out_size)
{
    (void)in_sizes; (void)n_in; (void)out_size;
    const float* query = (const float*)d_in[0];
    const float* key_  = (const float*)d_in[1];
    const float* value = (const float*)d_in[2];
    const float* Wq    = (const float*)d_in[3];
    const float* bq    = (const float*)d_in[4];
    const float* Wk    = (const float*)d_in[5];
    const float* bk    = (const float*)d_in[6];
    const float* Wv    = (const float*)d_in[7];
    const float* bv    = (const float*)d_in[8];
    float* out = (float*)d_out;

    float *dQ, *dK, *dV, *dS;
    cudaGetSymbolAddress((void**)&dQ, g_Q);
    cudaGetSymbolAddress((void**)&dK, g_K);
    cudaGetSymbolAddress((void**)&dV, g_V);
    cudaGetSymbolAddress((void**)&dS, g_S);

    static bool attr_done = false;
    if (!attr_done) {
        cudaFuncSetAttribute(mma_proj3_k,
                             cudaFuncAttributeMaxDynamicSharedMemorySize, GEMM_SMEM_BYTES);
        cudaFuncSetAttribute(mma_gemm_k<false, false>,
                             cudaFuncAttributeMaxDynamicSharedMemorySize, GEMM_SMEM_BYTES);
        cudaFuncSetAttribute(mma_gemm_k<true, false>,
                             cudaFuncAttributeMaxDynamicSharedMemorySize, GEMM_SMEM_BYTES);
        attr_done = true;
    }

    const long long sQK = (long long)SEQ * DMODEL;
    const long long sS  = (long long)SEQ * SEQ;
    dim3 thr(256);

    // 1) Projections (fused, grid.z picks q/k/v)
    dim3 gProj(DMODEL / 128, (BATCH * SEQ) / 128, 3);
    mma_proj3_k<<<gProj, thr, GEMM_SMEM_BYTES>>>(
        query, key_, value, Wq, bq, Wk, bk, Wv, bv, dQ, dK, dV);

    // 2) Scores: S = 8 * Q @ K^T (K matrix is K-major [N,K] -> direct)
    dim3 gScore(SEQ / 128, SEQ / 128, BATCH);
    mma_gemm_k<false, false><<<gScore, thr, GEMM_SMEM_BYTES>>>(
        dQ, dK, nullptr, dS, DMODEL, DMODEL, DMODEL, SEQ, 8.0f, sQK, sQK, sS);

    // 3) Softmax + threefry dropout (in place on S)
    dim3 gSm(SEQ, BATCH, 1);
    softmax_dropout_k<<<gSm, thr>>>(dS);

    // 4) Output: O = P @ V  (V is MN-major [K=2048, N=1024] -> transpose-load)
    dim3 gOut(DMODEL / 128, SEQ / 128, BATCH);
    mma_gemm_k<true, false><<<gOut, thr, GEMM_SMEM_BYTES>>>(
        dS, dV, nullptr, out, SEQ, SEQ, DMODEL, DMODEL, 1.0f, sS, sQK, sQK);
}

// round 6
// speedup vs baseline: 1.8207x; 1.0834x over previous
#include <cuda_runtime.h>
#include <cstdint>

// ---------------------------------------------------------------------------
// Problem constants
// ---------------------------------------------------------------------------
#define BATCH  4
#define SEQ    2048
#define DMODEL 1024

// Scratch (device globals: allocation-free)
__device__ float g_Q[(size_t)BATCH * SEQ * DMODEL];
__device__ float g_K[(size_t)BATCH * SEQ * DMODEL];
__device__ float g_V[(size_t)BATCH * SEQ * DMODEL];
__device__ float g_S[(size_t)BATCH * SEQ * SEQ];

// ---------------------------------------------------------------------------
// Helpers
// ---------------------------------------------------------------------------
__device__ __forceinline__ uint32_t smem_u32(const void* p) {
    uint32_t a;
    asm("{ .reg .u64 t; cvta.to.shared.u64 t, %1; cvt.u32.u64 %0, t; }"
        : "=r"(a) : "l"(p));
    return a;
}

#define CP_ASYNC16(saddr, gptr) \
    asm volatile("cp.async.cg.shared.global [%0], [%1], 16;" \
        :: "r"(saddr), "l"(gptr) : "memory")
#define CP_COMMIT() asm volatile("cp.async.commit_group;" ::: "memory")
#define CP_WAIT0()  asm volatile("cp.async.wait_group 0;" ::: "memory")
#define CP_WAIT1()  asm volatile("cp.async.wait_group 1;" ::: "memory")

// tf32x3 split: hi = top 10 mantissa bits (valid tf32), lo = rounded residual
__device__ __forceinline__ void split3(float x, uint32_t& hi, uint32_t& lo) {
    const uint32_t h = __float_as_uint(x) & 0xffffe000u;
    hi = h;
    const float l = x - __uint_as_float(h);
    uint32_t lt;
    asm("cvt.rna.tf32.f32 %0, %1;" : "=r"(lt) : "f"(l));
    lo = lt;
}

// plain tf32 round (for x2 B operand)
__device__ __forceinline__ uint32_t to_tf32(float x) {
    uint32_t t;
    asm("cvt.rna.tf32.f32 %0, %1;" : "=r"(t) : "f"(x));
    return t;
}

// D += A(16x8 tf32) * B(8x8 tf32), fp32 accumulate
__device__ __forceinline__ void mma8(float* d, const uint32_t* a, const uint32_t* b) {
    asm volatile(
        "mma.sync.aligned.m16n8k8.row.col.f32.tf32.tf32.f32 "
        "{%0,%1,%2,%3}, {%4,%5,%6,%7}, {%8,%9}, {%0,%1,%2,%3};"
        : "+f"(d[0]), "+f"(d[1]), "+f"(d[2]), "+f"(d[3])
        : "r"(a[0]), "r"(a[1]), "r"(a[2]), "r"(a[3]), "r"(b[0]), "r"(b[1]));
}

// ---------------------------------------------------------------------------
// tf32 emulated GEMM body: C[m,n] = alpha * sum_k A[m,k]*Bmat[k,n] (+ bias[n])
//   TRANSB_LOAD=false: Bmat[k,n] = B[n*ldb + k]  (B K-major [N,K], e.g. K^T)
//   TRANSB_LOAD=true : Bmat[k,n] = B[k*ldb + n]  (B MN-major [K,N], e.g. W, V)
//   SCHEME=3: D += Ah*Bh + Ah*Bl + Al*Bh   (fp32-accurate, ~2^-21/term)
//   SCHEME=2: D += Ah*Bt + Al*Bt           (A exact, B rounded to tf32 ~2^-12)
// BM=BN=128, KC=32, 256 threads (8 warps, each 64x32), cp.async 2-stage.
// ---------------------------------------------------------------------------
#define A_TILE_F 4608            // 128 * 36 floats
#define B_TILE_F 4608            // >= max(128*36 direct, 32*136 trans)
#define STAGE_F  (A_TILE_F + B_TILE_F)
#define GEMM_SMEM_BYTES (2 * STAGE_F * 4)

template <bool TRANSB_LOAD, bool HASBIAS, int SCHEME>
__device__ __forceinline__
void gemm_body(const float* __restrict__ A, const float* __restrict__ B,
               const float* __restrict__ bias, float* __restrict__ C,
               int K, int lda, int ldb, int ldc, float alpha)
{
    extern __shared__ float smem[];

    const int tid  = threadIdx.x;
    const int wid  = tid >> 5;
    const int lane = tid & 31;
    const int tg   = lane >> 2;      // 0..7
    const int tk   = lane & 3;       // 0..3
    const int row0 = blockIdx.y * 128;
    const int col0 = blockIdx.x * 128;
    const int wm   = (wid >> 2) * 64;   // warp m-offset in tile
    const int wn   = (wid & 3) * 32;    // warp n-offset in tile

    float acc[4][4][4];
#pragma unroll
    for (int mt = 0; mt < 4; mt++)
#pragma unroll
        for (int nt = 0; nt < 4; nt++)
#pragma unroll
            for (int e = 0; e < 4; e++) acc[mt][nt][e] = 0.0f;

    // ---- stage fill via cp.async ----
    auto fill = [&](int st, int k0) {
        float* base = smem + st * STAGE_F;
        const uint32_t sAa = smem_u32(base);
        const uint32_t sBa = smem_u32(base + A_TILE_F);
        // A tile: [128 m][32 k], k-contiguous global
#pragma unroll
        for (int j = 0; j < 4; j++) {
            const int idx = tid + j * 256;
            const int r  = idx >> 3;
            const int c4 = (idx & 7) << 2;
            CP_ASYNC16(sAa + (uint32_t)(r * 36 + c4) * 4u,
                       A + (size_t)(row0 + r) * lda + k0 + c4);
        }
        if (TRANSB_LOAD) {
            // B global [K,N] n-contiguous -> smem [32 k][128 n], ld=136
#pragma unroll
            for (int j = 0; j < 4; j++) {
                const int idx = tid + j * 256;
                const int kk = idx >> 5;
                const int n4 = (idx & 31) << 2;
                CP_ASYNC16(sBa + (uint32_t)(kk * 136 + n4) * 4u,
                           B + (size_t)(k0 + kk) * ldb + col0 + n4);
            }
        } else {
            // B global [N,K] k-contiguous -> smem [128 n][32 k], ld=36
#pragma unroll
            for (int j = 0; j < 4; j++) {
                const int idx = tid + j * 256;
                const int r  = idx >> 3;
                const int c4 = (idx & 7) << 2;
                CP_ASYNC16(sBa + (uint32_t)(r * 36 + c4) * 4u,
                           B + (size_t)(col0 + r) * ldb + k0 + c4);
            }
        }
        CP_COMMIT();
    };

    // ---- compute one staged chunk (4 k8-steps), register-lean order ----
    auto compute = [&](int st) {
        const float* sA = smem + st * STAGE_F;
        const float* sB = sA + A_TILE_F;
#pragma unroll
        for (int s = 0; s < 4; s++) {
            // B fragments for all 4 nt
            uint32_t bh[4][2], bl[4][2];
#pragma unroll
            for (int nt = 0; nt < 4; nt++) {
                const int n0 = wn + nt * 8;
                float b0, b1;
                if (TRANSB_LOAD) {
                    b0 = sB[(s * 8 + tk)     * 136 + n0 + tg];
                    b1 = sB[(s * 8 + tk + 4) * 136 + n0 + tg];
                } else {
                    b0 = sB[(n0 + tg) * 36 + s * 8 + tk];
                    b1 = sB[(n0 + tg) * 36 + s * 8 + tk + 4];
                }
                if (SCHEME == 3) {
                    split3(b0, bh[nt][0], bl[nt][0]);
                    split3(b1, bh[nt][1], bl[nt][1]);
                } else {
                    bh[nt][0] = to_tf32(b0);
                    bh[nt][1] = to_tf32(b1);
                }
            }
            // A fragments per mt
#pragma unroll
            for (int mt = 0; mt < 4; mt++) {
                const int m0 = wm + mt * 16;
                uint32_t ah[4], al[4];
                const float a0 = sA[(m0 + tg)     * 36 + s * 8 + tk];
                const float a1 = sA[(m0 + tg + 8) * 36 + s * 8 + tk];
                const float a2 = sA[(m0 + tg)     * 36 + s * 8 + tk + 4];
                const float a3 = sA[(m0 + tg + 8) * 36 + s * 8 + tk + 4];
                split3(a0, ah[0], al[0]);
                split3(a1, ah[1], al[1]);
                split3(a2, ah[2], al[2]);
                split3(a3, ah[3], al[3]);
#pragma unroll
                for (int nt = 0; nt < 4; nt++) {
                    mma8(acc[mt][nt], ah, bh[nt]);
                    if (SCHEME == 3) mma8(acc[mt][nt], ah, bl[nt]);
                    mma8(acc[mt][nt], al, bh[nt]);
                }
            }
        }
    };

    const int nchunk = K >> 5;   // K/32
    fill(0, 0);
    for (int i = 0; i < nchunk; i++) {
        if (i + 1 < nchunk) {
            fill((i + 1) & 1, (i + 1) << 5);
            CP_WAIT1();
        } else {
            CP_WAIT0();
        }
        __syncthreads();
        compute(i & 1);
        __syncthreads();
    }

    // ---- epilogue ----
#pragma unroll
    for (int mt = 0; mt < 4; mt++) {
        const int r = row0 + wm + mt * 16 + tg;
#pragma unroll
        for (int nt = 0; nt < 4; nt++) {
            const int col = col0 + wn + nt * 8 + tk * 2;
            float2 v0, v1;
            v0.x = acc[mt][nt][0] * alpha;
            v0.y = acc[mt][nt][1] * alpha;
            v1.x = acc[mt][nt][2] * alpha;
            v1.y = acc[mt][nt][3] * alpha;
            if (HASBIAS) {
                const float b0 = bias[col], b1 = bias[col + 1];
                v0.x += b0; v0.y += b1;
                v1.x += b0; v1.y += b1;
            }
            *(float2*)(C + (size_t)r * ldc + col)       = v0;
            *(float2*)(C + (size_t)(r + 8) * ldc + col) = v1;
        }
    }
}

// Generic batched GEMM kernel (2 CTAs/SM)
template <bool TRANSB_LOAD, bool HASBIAS, int SCHEME>
__global__ __launch_bounds__(256, 2)
void mma_gemm_k(const float* __restrict__ Ag, const float* __restrict__ Bg,
                const float* __restrict__ bias, float* __restrict__ Cg,
                int K, int lda, int ldb, int ldc, float alpha,
                long long sA, long long sB, long long sC)
{
    const int z = blockIdx.z;
    gemm_body<TRANSB_LOAD, HASBIAS, SCHEME>(Ag + (long long)z * sA,
                                            Bg + (long long)z * sB,
                                            bias, Cg + (long long)z * sC,
                                            K, lda, ldb, ldc, alpha);
}

// Fused Q/K/V projection: blockIdx.z picks which projection
__global__ __launch_bounds__(256, 2)
void mma_proj3_k(const float* __restrict__ q, const float* __restrict__ k,
                 const float* __restrict__ v,
                 const float* __restrict__ Wq, const float* __restrict__ bq,
                 const float* __restrict__ Wk, const float* __restrict__ bk,
                 const float* __restrict__ Wv, const float* __restrict__ bv,
                 float* __restrict__ Q, float* __restrict__ K, float* __restrict__ V)
{
    const float *A, *B, *bias;
    float* C;
    if (blockIdx.z == 0)      { A = q; B = Wq; bias = bq; C = Q; }
    else if (blockIdx.z == 1) { A = k; B = Wk; bias = bk; C = K; }
    else                      { A = v; B = Wv; bias = bv; C = V; }
    gemm_body<true, true, 3>(A, B, bias, C, DMODEL, DMODEL, DMODEL, DMODEL, 1.0f);
}

// ---------------------------------------------------------------------------
// JAX threefry2x32, key (0,42), partitionable scheme:
//   bits[i] = y0 ^ y1 of threefry2x32(key, (0, i)); keep <=> MSB==0
// ---------------------------------------------------------------------------
__device__ __forceinline__ uint32_t threefry_mask_word(uint32_t idx)
{
    const uint32_t ks0 = 0u;
    const uint32_t ks1 = 42u;
    const uint32_t ks2 = 42u ^ 0x1BD11BDAu;
    uint32_t x0 = ks0;
    uint32_t x1 = idx + ks1;
#define TFR(r) { x0 += x1; x1 = __funnelshift_l(x1, x1, (r)); x1 ^= x0; }
    TFR(13) TFR(15) TFR(26) TFR(6)
    x0 += ks1; x1 += ks2 + 1u;
    TFR(17) TFR(29) TFR(16) TFR(24)
    x0 += ks2; x1 += ks0 + 2u;
    TFR(13) TFR(15) TFR(26) TFR(6)
    x0 += ks0; x1 += ks1 + 3u;
    TFR(17) TFR(29) TFR(16) TFR(24)
    x0 += ks1; x1 += ks2 + 4u;
    TFR(13) TFR(15) TFR(26) TFR(6)
    x0 += ks2; x1 += ks0 + 5u;
#undef TFR
    return x0 ^ x1;
}

// ---------------------------------------------------------------------------
// Softmax + dropout, one block per (b,q) row of S. kept value scaled by 2.
// ---------------------------------------------------------------------------
__global__ __launch_bounds__(256, 4)
void softmax_dropout_k(float* __restrict__ S)
{
    const int q   = blockIdx.x;
    const int b   = blockIdx.y;
    const int tid = threadIdx.x;
    float* __restrict__ row = S + ((size_t)b * SEQ + q) * SEQ;

    float a[8];
#pragma unroll
    for (int j = 0; j < 8; j++) a[j] = row[tid + j * 256];

    float m = a[0];
#pragma unroll
    for (int j = 1; j < 8; j++) m = fmaxf(m, a[j]);
#pragma unroll
    for (int s = 16; s > 0; s >>= 1)
        m = fmaxf(m, __shfl_xor_sync(0xffffffffu, m, s));
    __shared__ float red[8];
    const int wid = tid >> 5, lane = tid & 31;
    if (lane == 0) red[wid] = m;
    __syncthreads();
    m = red[0];
#pragma unroll
    for (int w = 1; w < 8; w++) m = fmaxf(m, red[w]);
    __syncthreads();

    float s0 = 0.0f;
#pragma unroll
    for (int j = 0; j < 8; j++) {
        a[j] = __expf(a[j] - m);
        s0 += a[j];
    }
#pragma unroll
    for (int s = 16; s > 0; s >>= 1)
        s0 += __shfl_xor_sync(0xffffffffu, s0, s);
    if (lane == 0) red[wid] = s0;
    __syncthreads();
    s0 = 0.0f;
#pragma unroll
    for (int w = 0; w < 8; w++) s0 += red[w];

    const float inv = 2.0f / s0;

    const uint32_t base = ((uint32_t)(b * SEQ + q)) * (uint32_t)SEQ;
#pragma unroll
    for (int j = 0; j < 8; j++) {
        const uint32_t k = (uint32_t)tid + (uint32_t)j * 256u;
        const uint32_t w = threefry_mask_word(base + k);
        row[k] = (w >> 31) ? 0.0f : a[j] * inv;
    }
}

// ---------------------------------------------------------------------------
// Launcher
// ---------------------------------------------------------------------------
extern "C" void kernel_launch(void* const* d_in, const int* in_sizes, int n_in,
                              void* d_out, int out_size)
{
    (void)in_sizes; (void)n_in; (void)out_size;
    const float* query = (const float*)d_in[0];
    const float* key_  = (const float*)d_in[1];
    const float* value = (const float*)d_in[2];
    const float* Wq    = (const float*)d_in[3];
    const float* bq    = (const float*)d_in[4];
    const float* Wk    = (const float*)d_in[5];
    const float* bk    = (const float*)d_in[6];
    const float* Wv    = (const float*)d_in[7];
    const float* bv    = (const float*)d_in[8];
    float* out = (float*)d_out;

    float *dQ, *dK, *dV, *dS;
    cudaGetSymbolAddress((void**)&dQ, g_Q);
    cudaGetSymbolAddress((void**)&dK, g_K);
    cudaGetSymbolAddress((void**)&dV, g_V);
    cudaGetSymbolAddress((void**)&dS, g_S);

    static bool attr_done = false;
    if (!attr_done) {
        cudaFuncSetAttribute(mma_proj3_k,
                             cudaFuncAttributeMaxDynamicSharedMemorySize, GEMM_SMEM_BYTES);
        cudaFuncSetAttribute(mma_gemm_k<false, false, 3>,
                             cudaFuncAttributeMaxDynamicSharedMemorySize, GEMM_SMEM_BYTES);
        cudaFuncSetAttribute(mma_gemm_k<true, false, 2>,
                             cudaFuncAttributeMaxDynamicSharedMemorySize, GEMM_SMEM_BYTES);
        attr_done = true;
    }

    const long long sQK = (long long)SEQ * DMODEL;
    const long long sS  = (long long)SEQ * SEQ;
    dim3 thr(256);

    // 1) Projections (fused, grid.z picks q/k/v) — tf32x3
    dim3 gProj(DMODEL / 128, (BATCH * SEQ) / 128, 3);
    mma_proj3_k<<<gProj, thr, GEMM_SMEM_BYTES>>>(
        query, key_, value, Wq, bq, Wk, bk, Wv, bv, dQ, dK, dV);

    // 2) Scores: S = 8 * Q @ K^T — tf32x3 (precision-critical path)
    dim3 gScore(SEQ / 128, SEQ / 128, BATCH);
    mma_gemm_k<false, false, 3><<<gScore, thr, GEMM_SMEM_BYTES>>>(
        dQ, dK, nullptr, dS, DMODEL, DMODEL, DMODEL, SEQ, 8.0f, sQK, sQK, sS);

    // 3) Softmax + threefry dropout (in place on S)
    dim3 gSm(SEQ, BATCH, 1);
    softmax_dropout_k<<<gSm, thr>>>(dS);

    // 4) Output: O = P @ V — tf32x2 (P split exactly, V rounded: ~2e-4 rel)
    dim3 gOut(DMODEL / 128, SEQ / 128, BATCH);
    mma_gemm_k<true, false, 2><<<gOut, thr, GEMM_SMEM_BYTES>>>(
        dS, dV, nullptr, out, SEQ, SEQ, DMODEL, DMODEL, 1.0f, sS, sQK, sQK);
}